// round 3
// baseline (speedup 1.0000x reference)
#include <cuda_runtime.h>
#include <cuda_bf16.h>
#include <math.h>

#define FULL_MASK 0xFFFFFFFFu

// Scratch: chosen FPS indices and the encoded distance matrix
// (bs*n*n = 4*2048*2048 uint32 = 64 MB; fits in GB300's ~126 MB L2).
__device__ int      g_qidx[8192];
__device__ unsigned g_dm[4L * 2048 * 2048];

// ---------------------------------------------------------------------------
// Mask dtype handling (bool may arrive as u8 / i32 / f32; mask[0] is True).
// ---------------------------------------------------------------------------
static __device__ __forceinline__ int mask_mode(const void* mask) {
    unsigned u0 = *(const unsigned*)mask;
    if (u0 == 0x3F800000u) return 2;   // f32
    if (u0 == 1u)          return 1;   // i32
    return 0;                          // byte
}
static __device__ __forceinline__ bool mask_at(const void* mask, int mode, long idx) {
    if (mode == 0) return ((const unsigned char*)mask)[idx] != 0;
    if (mode == 1) return ((const int*)mask)[idx] != 0;
    return ((const float*)mask)[idx] != 0.0f;
}

// Monotone (order-preserving) float -> uint32 encoding.
// For this problem's values: enc(norm>=0) >= 0x80000000, enc(-100)=0x3D37FFFF.
// => encoded values are NEVER 0, so 0 is a safe "row not written" sentinel.
static __device__ __forceinline__ unsigned enc_f32(float f) {
    unsigned u = __float_as_uint(f);
    unsigned s = (unsigned)((int)u >> 31);
    return u ^ (s | 0x80000000u);
}
// Shared by the precompute path and the FPS fallback path: MUST be the same
// inline function so both produce bit-identical encodings.
static __device__ __forceinline__ unsigned enc_norm(float4 v, bool mk) {
    float nrm = sqrtf(v.x*v.x + v.y*v.y + v.z*v.z + v.w*v.w);
    return enc_f32(mk ? nrm : -100.0f);
}

// ---------------------------------------------------------------------------
// Zero the dm (sentinel state) each call — keeps replays deterministic.
// ---------------------------------------------------------------------------
__global__ void zero_dm_kernel(size_t total_u4) {
    size_t idx    = (size_t)blockIdx.x * blockDim.x + threadIdx.x;
    size_t stride = (size_t)gridDim.x * blockDim.x;
    const uint4 z = make_uint4(0u, 0u, 0u, 0u);
    for (; idx < total_u4; idx += stride)
        ((uint4*)g_dm)[idx] = z;
}

// ---------------------------------------------------------------------------
// Fused kernel: blocks [0, bs) run the sequential FPS chain; blocks
// [bs, bs + bs*n) each encode ONE dm row (b = r % bs so batches progress
// uniformly). FPS reads dm rows; a zero word means "not written yet" and the
// thread recomputes its 4 encodings directly from abq (identical bits).
// ---------------------------------------------------------------------------
__global__ void __launch_bounds__(512, 2)
fused_kernel(const float4* __restrict__ abq, const void* __restrict__ mask,
             const int* __restrict__ rand_start, int n, int m, int bs) {
    const int tid  = threadIdx.x;
    const int mode = mask_mode(mask);
    const int nq   = n >> 2;

    if ((int)blockIdx.x >= bs) {
        // ---------------- precompute: one row per block ----------------
        int r = blockIdx.x - bs;
        int b = r % bs;
        int i = r / bs;
        size_t row = (size_t)b * n + i;
        const float4* src = abq + row * n + 4 * tid;   // 64B contiguous/thread
        long mb = (long)b * n + 4 * tid;
        float4 a0 = __ldg(src + 0), a1 = __ldg(src + 1),
               a2 = __ldg(src + 2), a3 = __ldg(src + 3);
        uint4 o;
        o.x = enc_norm(a0, mask_at(mask, mode, mb + 0));
        o.y = enc_norm(a1, mask_at(mask, mode, mb + 1));
        o.z = enc_norm(a2, mask_at(mask, mode, mb + 2));
        o.w = enc_norm(a3, mask_at(mask, mode, mb + 3));
        ((uint4*)g_dm)[row * nq + tid] = o;            // single STG.128
        return;
    }

    // ---------------- FPS: one block per batch ----------------
    const int b    = blockIdx.x;
    const int lane = tid & 31;
    const int warp = tid >> 5;                         // 0..15

    __shared__ unsigned char s_mask[2048];
    __shared__ unsigned      s_key[32];                // [2][16] double-buffered
    __shared__ int           s_idx[32];
    __shared__ int           s_far;

    const long mbase = (long)b * n;
    for (int j = tid; j < n; j += 512)
        s_mask[j] = mask_at(mask, mode, mbase + j) ? 1 : 0;
    __syncthreads();

    // Initial farthest = index of k-th True, k = rand_start[b] % count.
    if (tid < 32) {
        const int chunk = (n + 31) / 32;
        const int base  = lane * chunk;
        int cnt = 0;
        for (int i = 0; i < chunk; i++) {
            int jj = base + i;
            if (jj < n) cnt += s_mask[jj];
        }
        int inc = cnt;
        #pragma unroll
        for (int off = 1; off < 32; off <<= 1) {
            int v = __shfl_up_sync(FULL_MASK, inc, off);
            if (lane >= off) inc += v;
        }
        const int total = __shfl_sync(FULL_MASK, inc, 31);
        const int k     = rand_start[b] % total;
        const int excl  = inc - cnt;
        if (k >= excl && k < inc) {
            int need = k - excl;
            for (int i = 0; i < chunk; i++) {
                int jj = base + i;
                if (jj < n && s_mask[jj]) {
                    if (need == 0) { s_far = jj; break; }
                    need--;
                }
            }
        }
    }
    __syncthreads();
    int far = s_far;

    // Per-thread mask bits for blocked columns 4*tid .. 4*tid+3 (fallback).
    const bool mk0 = s_mask[4 * tid + 0] != 0;
    const bool mk1 = s_mask[4 * tid + 1] != 0;
    const bool mk2 = s_mask[4 * tid + 2] != 0;
    const bool mk3 = s_mask[4 * tid + 3] != 0;

    const unsigned E_INIT = enc_f32(1e8f);
    uint4 dist = make_uint4(E_INIT, E_INIT, E_INIT, E_INIT);

    const uint4*  dmb   = (const uint4*)g_dm + (size_t)b * n * nq;
    const float4* abq_b = abq + (size_t)b * n * n;

    for (int t = 0; t < m; t++) {
        // Row read: 8 KB from L2 once precomputed; self-validating sentinel.
        uint4 v = __ldg(dmb + (size_t)far * nq + tid);
        if (tid == 0) g_qidx[b * m + t] = far;

        if (min(min(v.x, v.y), min(v.z, v.w)) == 0u) {
            // Row not (fully) written yet: recompute own 4 encodings from abq.
            const float4* arow = abq_b + (size_t)far * n + 4 * tid;
            v.x = enc_norm(__ldg(arow + 0), mk0);
            v.y = enc_norm(__ldg(arow + 1), mk1);
            v.z = enc_norm(__ldg(arow + 2), mk2);
            v.w = enc_norm(__ldg(arow + 3), mk3);
        }

        dist.x = min(dist.x, v.x);
        dist.y = min(dist.y, v.y);
        dist.z = min(dist.z, v.z);
        dist.w = min(dist.w, v.w);

        // Local argmax over 4 (tie -> lowest j).
        unsigned bk = dist.x; int bj = 0;
        if (dist.y > bk) { bk = dist.y; bj = 1; }
        if (dist.z > bk) { bk = dist.z; bj = 2; }
        if (dist.w > bk) { bk = dist.w; bj = 3; }
        bj += tid << 2;

        // Warp argmax via REDUX; tie -> lowest lane == lowest j (blocked).
        unsigned mk   = __reduce_max_sync(FULL_MASK, bk);
        unsigned ball = __ballot_sync(FULL_MASK, bk == mk);
        int src       = __ffs(ball) - 1;
        int wj        = __shfl_sync(FULL_MASK, bj, src);
        const int buf = (t & 1) << 4;
        if (lane == 0) { s_key[buf + warp] = mk; s_idx[buf + warp] = wj; }
        __syncthreads();

        // Redundant final reduce in EVERY warp (double-buffered slots ->
        // next iteration's own barrier fences reuse; no second barrier).
        unsigned k2 = 0; int j2 = 0;
        if (lane < 16) { k2 = s_key[buf + lane]; j2 = s_idx[buf + lane]; }
        unsigned mk2   = __reduce_max_sync(FULL_MASK, k2);
        unsigned ball2 = __ballot_sync(FULL_MASK, k2 == mk2);
        int src2       = __ffs(ball2) - 1;
        far            = __shfl_sync(FULL_MASK, j2, src2);
    }
}

// ---------------------------------------------------------------------------
// Merged gathers: pairs (sub_abq float4 + sub_edges float2) then small
// (sub_vals float4 chunks + sub_mask) in one launch.
// ---------------------------------------------------------------------------
__global__ void gather_kernel(const float4* __restrict__ abq,
                              const float2* __restrict__ edges,
                              const float4* __restrict__ vals4,
                              const void* __restrict__ mask,
                              float4* __restrict__ out_abq,
                              float2* __restrict__ out_edges,
                              float4* __restrict__ out_vals,
                              float* __restrict__ out_mask,
                              int n, int m, int bs, int c4) {
    int idx = blockIdx.x * blockDim.x + threadIdx.x;
    int total_pairs = bs * m * m;
    if (idx < total_pairs) {
        int j = idx % m;
        int r = idx / m;
        int i = r % m;
        int b = r / m;
        int qi = g_qidx[b * m + i];
        int qj = g_qidx[b * m + j];
        size_t src = ((size_t)b * n + (size_t)qi) * (size_t)n + (size_t)qj;
        out_abq[idx]   = __ldg(abq + src);
        out_edges[idx] = __ldg(edges + src);
    } else {
        int k = idx - total_pairs;
        if (k >= bs * m * c4) return;
        int ch = k % c4;
        int r  = k / c4;
        int i  = r % m;
        int b  = r / m;
        int qi = g_qidx[b * m + i];
        out_vals[k] = __ldg(vals4 + ((size_t)b * n + (size_t)qi) * (size_t)c4 + ch);
        if (ch == 0) {
            int mode = mask_mode(mask);
            out_mask[b * m + i] = mask_at(mask, mode, (long)b * n + qi) ? 1.0f : 0.0f;
        }
    }
}

// ---------------------------------------------------------------------------
// Launch. Inputs: abq_pairs f32 (bs,n,n,4), vals f32 (bs,n,64), mask bool
// (bs,n), edges f32 (bs,n,n,2), rand_start i32 (bs).
// Output: [sub_abq | sub_vals | sub_mask | sub_edges] as f32.
// ---------------------------------------------------------------------------
extern "C" void kernel_launch(void* const* d_in, const int* in_sizes, int n_in,
                              void* d_out, int out_size) {
    const float4* abq   = (const float4*)d_in[0];
    const float4* vals4 = (const float4*)d_in[1];
    const void*   mask  = (const void*)d_in[2];
    const float2* edges = (const float2*)d_in[3];
    const int*    rnd   = (const int*)d_in[4];

    const int bs = in_sizes[4];                 // 4
    const int n  = in_sizes[2] / bs;            // 2048
    const int m  = n / 4;                       // 512
    const int c  = in_sizes[1] / (bs * n);      // 64
    const int c4 = c / 4;

    float* out = (float*)d_out;
    float4* out_abq    = (float4*)out;
    float*  out_vals_f = out + (size_t)bs * m * m * 4;
    float*  out_mask   = out_vals_f + (size_t)bs * m * c;
    float2* out_edges  = (float2*)(out_mask + (size_t)bs * m);

    // 1) Reset dm to the zero sentinel (determinism across graph replays).
    size_t total_u4 = (size_t)bs * n * n / 4;
    zero_dm_kernel<<<2048, 256>>>(total_u4);

    // 2) Fused: FPS chain (blocks 0..bs-1) overlapped with row precompute.
    fused_kernel<<<bs + bs * n, 512>>>(abq, mask, rnd, n, m, bs);

    // 3) Merged output gathers.
    int total = bs * m * m + bs * m * c4;
    gather_kernel<<<(total + 255) / 256, 256>>>(
        abq, edges, vals4, mask,
        out_abq, out_edges, (float4*)out_vals_f, out_mask, n, m, bs, c4);
}

// round 4
// speedup vs baseline: 1.7061x; 1.7061x over previous
#include <cuda_runtime.h>
#include <cuda_bf16.h>
#include <math.h>

#define FULL_MASK 0xFFFFFFFFu

// Scratch: chosen FPS indices and the encoded distance matrix
// (bs*n*n = 4*2048*2048 uint32 = 64 MB; fits in GB300's ~126 MB L2).
__device__ int      g_qidx[8192];
__device__ unsigned g_dm[4L * 2048 * 2048];

// ---------------------------------------------------------------------------
// Mask dtype handling (bool may arrive as u8 / i32 / f32; mask[0] is True).
// ---------------------------------------------------------------------------
static __device__ __forceinline__ int mask_mode(const void* mask) {
    unsigned u0 = *(const unsigned*)mask;
    if (u0 == 0x3F800000u) return 2;   // f32
    if (u0 == 1u)          return 1;   // i32
    return 0;                          // byte
}
static __device__ __forceinline__ bool mask_at(const void* mask, int mode, long idx) {
    if (mode == 0) return ((const unsigned char*)mask)[idx] != 0;
    if (mode == 1) return ((const int*)mask)[idx] != 0;
    return ((const float*)mask)[idx] != 0.0f;
}

// Monotone (order-preserving) float -> uint32 encoding. All values arising
// here (norms >= 0, -100, 1e8) encode to nonzero.
static __device__ __forceinline__ unsigned enc_f32(float f) {
    unsigned u = __float_as_uint(f);
    unsigned s = (unsigned)((int)u >> 31);
    return u ^ (s | 0x80000000u);
}

// Volatile 8B shared-memory accessors for the spin-sync slots.
static __device__ __forceinline__ void sts_vol_u64(unsigned addr, unsigned long long v) {
    asm volatile("st.volatile.shared.b64 [%0], %1;" :: "r"(addr), "l"(v));
}
static __device__ __forceinline__ unsigned long long lds_vol_u64(unsigned addr) {
    unsigned long long v;
    asm volatile("ld.volatile.shared.b64 %0, [%1];" : "=l"(v) : "r"(addr));
    return v;
}

// ---------------------------------------------------------------------------
// Precompute: g_dm[b,i,j] = enc( mask[b,j] ? ||abq[b,i,j,:]|| : -100 ).
// One thread per 4 consecutive j. abq read with streaming hint (evict-first)
// so the 256 MB input stream does not evict the 64 MB dm from L2.
// ---------------------------------------------------------------------------
__global__ void precompute_kernel(const float4* __restrict__ abq,
                                  const void* __restrict__ mask,
                                  int n, int total4) {
    int idx = blockIdx.x * blockDim.x + threadIdx.x;
    if (idx >= total4) return;
    const int nq = n >> 2;
    int j4 = idx % nq;
    int r  = idx / nq;
    int b  = r / n;

    const int mode = mask_mode(mask);
    const float4* src = abq + (size_t)idx * 4;
    unsigned out[4];
    #pragma unroll
    for (int k = 0; k < 4; k++) {
        float4 v = __ldcs(src + k);                    // streaming: evict-first
        float nrm = sqrtf(v.x*v.x + v.y*v.y + v.z*v.z + v.w*v.w);
        bool mk = mask_at(mask, mode, (long)b * n + j4 * 4 + k);
        out[k] = enc_f32(mk ? nrm : -100.0f);
    }
    ((uint4*)g_dm)[idx] = make_uint4(out[0], out[1], out[2], out[3]);
}

// ---------------------------------------------------------------------------
// FPS: one block per batch, 512 threads, 4 j's per thread (blocked layout so
// lane/warp order == j order for first-occurrence tie-breaks).
// Cross-warp sync: tag-stamped double-buffered smem slots + spin (no BAR in
// the steady-state loop). Packed slot: key<<32 | tag<<11 | j  (j<2048 -> 11
// bits, tag=t+1<=512 -> 10 bits). Double buffering bounds warp skew to one
// iteration, so a slot is never overwritten before all warps consumed it.
// ---------------------------------------------------------------------------
__global__ void __launch_bounds__(512, 1)
fps_kernel(const void* __restrict__ mask, const int* __restrict__ rand_start,
           int n, int m) {
    const int b    = blockIdx.x;
    const int tid  = threadIdx.x;
    const int lane = tid & 31;
    const int warp = tid >> 5;                        // 0..15

    __shared__ unsigned char          s_mask[2048];
    __shared__ unsigned long long     s_slot[2][16];
    __shared__ int                    s_far;

    const int  mode  = mask_mode(mask);
    const long mbase = (long)b * n;
    for (int j = tid; j < n; j += 512)
        s_mask[j] = mask_at(mask, mode, mbase + j) ? 1 : 0;
    if (tid < 32) s_slot[tid >> 4][tid & 15] = 0ull;  // tag 0 != 1
    __syncthreads();

    // Initial farthest = index of k-th True, k = rand_start[b] % count.
    if (tid < 32) {
        const int chunk = (n + 31) / 32;
        const int base  = lane * chunk;
        int cnt = 0;
        for (int i = 0; i < chunk; i++) {
            int jj = base + i;
            if (jj < n) cnt += s_mask[jj];
        }
        int inc = cnt;
        #pragma unroll
        for (int off = 1; off < 32; off <<= 1) {
            int v = __shfl_up_sync(FULL_MASK, inc, off);
            if (lane >= off) inc += v;
        }
        const int total = __shfl_sync(FULL_MASK, inc, 31);
        const int k     = rand_start[b] % total;
        const int excl  = inc - cnt;
        if (k >= excl && k < inc) {
            int need = k - excl;
            for (int i = 0; i < chunk; i++) {
                int jj = base + i;
                if (jj < n && s_mask[jj]) {
                    if (need == 0) { s_far = jj; break; }
                    need--;
                }
            }
        }
    }
    __syncthreads();
    int far = s_far;

    const unsigned E_INIT = enc_f32(1e8f);
    uint4 dist = make_uint4(E_INIT, E_INIT, E_INIT, E_INIT);

    const int   nq  = n >> 2;
    const uint4* dmb = (const uint4*)g_dm + (size_t)b * n * nq;

    const unsigned slot_base =
        (unsigned)__cvta_generic_to_shared(&s_slot[0][0]);
    const unsigned my_slot_rd = slot_base + (unsigned)(lane & 15) * 8u;

    for (int t = 0; t < m; t++) {
        if (tid == 0) g_qidx[b * m + t] = far;

        // Row read: 8 KB from L2 (dm resident after precompute).
        uint4 v = __ldg(dmb + (size_t)far * nq + tid);
        dist.x = min(dist.x, v.x);
        dist.y = min(dist.y, v.y);
        dist.z = min(dist.z, v.z);
        dist.w = min(dist.w, v.w);

        // Local argmax over 4 (tie -> lowest j).
        unsigned bk = dist.x; int bj = 0;
        if (dist.y > bk) { bk = dist.y; bj = 1; }
        if (dist.z > bk) { bk = dist.z; bj = 2; }
        if (dist.w > bk) { bk = dist.w; bj = 3; }
        bj += tid << 2;

        // Warp argmax via REDUX; winner lane (lowest on tie -> lowest j,
        // blocked layout) stores the packed candidate directly. No shfl.
        const unsigned buf  = (unsigned)(t & 1);
        const unsigned tag  = (unsigned)(t + 1);
        unsigned mk   = __reduce_max_sync(FULL_MASK, bk);
        unsigned ball = __ballot_sync(FULL_MASK, bk == mk);
        int src       = __ffs(ball) - 1;
        if (lane == src) {
            unsigned long long pk = ((unsigned long long)mk << 32)
                                  | ((unsigned long long)tag << 11)
                                  | (unsigned)bj;
            sts_vol_u64(slot_base + (buf * 16u + (unsigned)warp) * 8u, pk);
        }

        // Spin until all 16 slots of this buffer carry this iteration's tag,
        // then reduce redundantly in every warp (lanes 0..15 hold slots).
        const unsigned rd = my_slot_rd + buf * 128u;
        unsigned long long pk = 0ull;
        bool ready;
        do {
            if (lane < 16) pk = lds_vol_u64(rd);
            unsigned tg = ((unsigned)pk >> 11) & 0x3FFu;
            ready = (lane >= 16) || (tg == tag);
        } while (!__all_sync(FULL_MASK, ready));

        unsigned k2 = (lane < 16) ? (unsigned)(pk >> 32) : 0u;  // keys != 0
        int      j2 = (int)((unsigned)pk & 0x7FFu);
        unsigned mk2   = __reduce_max_sync(FULL_MASK, k2);
        unsigned ball2 = __ballot_sync(FULL_MASK, k2 == mk2);
        int src2       = __ffs(ball2) - 1;                      // lowest warp
        far            = __shfl_sync(FULL_MASK, j2, src2);
    }
}

// ---------------------------------------------------------------------------
// Merged gathers: pairs (sub_abq float4 + sub_edges float2) then small
// (sub_vals float4 chunks + sub_mask) in one launch.
// ---------------------------------------------------------------------------
__global__ void gather_kernel(const float4* __restrict__ abq,
                              const float2* __restrict__ edges,
                              const float4* __restrict__ vals4,
                              const void* __restrict__ mask,
                              float4* __restrict__ out_abq,
                              float2* __restrict__ out_edges,
                              float4* __restrict__ out_vals,
                              float* __restrict__ out_mask,
                              int n, int m, int bs, int c4) {
    int idx = blockIdx.x * blockDim.x + threadIdx.x;
    int total_pairs = bs * m * m;
    if (idx < total_pairs) {
        int j = idx % m;
        int r = idx / m;
        int i = r % m;
        int b = r / m;
        int qi = g_qidx[b * m + i];
        int qj = g_qidx[b * m + j];
        size_t src = ((size_t)b * n + (size_t)qi) * (size_t)n + (size_t)qj;
        out_abq[idx]   = __ldcs(abq + src);
        out_edges[idx] = __ldcs(edges + src);
    } else {
        int k = idx - total_pairs;
        if (k >= bs * m * c4) return;
        int ch = k % c4;
        int r  = k / c4;
        int i  = r % m;
        int b  = r / m;
        int qi = g_qidx[b * m + i];
        out_vals[k] = __ldcs(vals4 + ((size_t)b * n + (size_t)qi) * (size_t)c4 + ch);
        if (ch == 0) {
            int mode = mask_mode(mask);
            out_mask[b * m + i] = mask_at(mask, mode, (long)b * n + qi) ? 1.0f : 0.0f;
        }
    }
}

// ---------------------------------------------------------------------------
// Launch. Inputs: abq_pairs f32 (bs,n,n,4), vals f32 (bs,n,64), mask bool
// (bs,n), edges f32 (bs,n,n,2), rand_start i32 (bs).
// Output: [sub_abq | sub_vals | sub_mask | sub_edges] as f32.
// ---------------------------------------------------------------------------
extern "C" void kernel_launch(void* const* d_in, const int* in_sizes, int n_in,
                              void* d_out, int out_size) {
    const float4* abq   = (const float4*)d_in[0];
    const float4* vals4 = (const float4*)d_in[1];
    const void*   mask  = (const void*)d_in[2];
    const float2* edges = (const float2*)d_in[3];
    const int*    rnd   = (const int*)d_in[4];

    const int bs = in_sizes[4];                 // 4
    const int n  = in_sizes[2] / bs;            // 2048
    const int m  = n / 4;                       // 512
    const int c  = in_sizes[1] / (bs * n);      // 64
    const int c4 = c / 4;

    float* out = (float*)d_out;
    float4* out_abq    = (float4*)out;
    float*  out_vals_f = out + (size_t)bs * m * m * 4;
    float*  out_mask   = out_vals_f + (size_t)bs * m * c;
    float2* out_edges  = (float2*)(out_mask + (size_t)bs * m);

    // 1) Precompute encoded masked-distance matrix (bandwidth-bound ~50us).
    int total4 = bs * n * (n / 4);
    precompute_kernel<<<(total4 + 255) / 256, 256>>>(abq, mask, n, total4);

    // 2) Sequential FPS on the L2-resident encoded matrix.
    fps_kernel<<<bs, 512>>>(mask, rnd, n, m);

    // 3) Merged output gathers.
    int total = bs * m * m + bs * m * c4;
    gather_kernel<<<(total + 255) / 256, 256>>>(
        abq, edges, vals4, mask,
        out_abq, out_edges, (float4*)out_vals_f, out_mask, n, m, bs, c4);
}

// round 5
// speedup vs baseline: 1.8945x; 1.1104x over previous
#include <cuda_runtime.h>
#include <cuda_bf16.h>
#include <math.h>

#define FULL_MASK 0xFFFFFFFFu

// Scratch: chosen FPS indices and the encoded distance matrix
// (bs*n*n = 4*2048*2048 uint32 = 64 MB; fits in GB300's ~126 MB L2).
__device__ int      g_qidx[8192];
__device__ unsigned g_dm[4L * 2048 * 2048];

// ---------------------------------------------------------------------------
// Mask dtype handling (bool may arrive as u8 / i32 / f32; mask[0] is True).
// ---------------------------------------------------------------------------
static __device__ __forceinline__ int mask_mode(const void* mask) {
    unsigned u0 = *(const unsigned*)mask;
    if (u0 == 0x3F800000u) return 2;   // f32
    if (u0 == 1u)          return 1;   // i32
    return 0;                          // byte
}
static __device__ __forceinline__ bool mask_at(const void* mask, int mode, long idx) {
    if (mode == 0) return ((const unsigned char*)mask)[idx] != 0;
    if (mode == 1) return ((const int*)mask)[idx] != 0;
    return ((const float*)mask)[idx] != 0.0f;
}

// Monotone (order-preserving) float -> uint32 encoding.
static __device__ __forceinline__ unsigned enc_f32(float f) {
    unsigned u = __float_as_uint(f);
    unsigned s = (unsigned)((int)u >> 31);
    return u ^ (s | 0x80000000u);
}

// ---------------------------------------------------------------------------
// Precompute: g_dm[b,i,j] = enc( mask[b,j] ? ||abq[b,i,j,:]|| : -100 ).
// One thread per 4 consecutive j. abq read with streaming hint (evict-first)
// so the 256 MB input stream does not evict the 64 MB dm from L2.
// ---------------------------------------------------------------------------
__global__ void precompute_kernel(const float4* __restrict__ abq,
                                  const void* __restrict__ mask,
                                  int n, int total4) {
    int idx = blockIdx.x * blockDim.x + threadIdx.x;
    if (idx >= total4) return;
    const int nq = n >> 2;
    int j4 = idx % nq;
    int r  = idx / nq;
    int b  = r / n;

    const int mode = mask_mode(mask);
    const float4* src = abq + (size_t)idx * 4;
    unsigned out[4];
    #pragma unroll
    for (int k = 0; k < 4; k++) {
        float4 v = __ldcs(src + k);                    // streaming: evict-first
        float nrm = sqrtf(v.x*v.x + v.y*v.y + v.z*v.z + v.w*v.w);
        bool mk = mask_at(mask, mode, (long)b * n + j4 * 4 + k);
        out[k] = enc_f32(mk ? nrm : -100.0f);
    }
    ((uint4*)g_dm)[idx] = make_uint4(out[0], out[1], out[2], out[3]);
}

// ---------------------------------------------------------------------------
// FPS: one block per batch, 512 threads, 4 j's per thread (blocked layout so
// lane/warp order == j order for first-occurrence tie-breaks).
// Per iter: 1 uint4 L2 load, 4 umin, local argmax, warp REDUX argmax,
// winner lane stores packed (key<<32 | j) u64 slot, ONE __syncthreads,
// redundant final reduce in every warp (double-buffered slots — the next
// iteration's own barrier fences slot reuse, so no second barrier needed).
// ---------------------------------------------------------------------------
__global__ void __launch_bounds__(512, 1)
fps_kernel(const void* __restrict__ mask, const int* __restrict__ rand_start,
           int n, int m) {
    const int b    = blockIdx.x;
    const int tid  = threadIdx.x;
    const int lane = tid & 31;
    const int warp = tid >> 5;                        // 0..15

    __shared__ unsigned char      s_mask[2048];
    __shared__ unsigned long long s_slot[2][16];      // packed key<<32 | j
    __shared__ int                s_far;

    const int  mode  = mask_mode(mask);
    const long mbase = (long)b * n;
    for (int j = tid; j < n; j += 512)
        s_mask[j] = mask_at(mask, mode, mbase + j) ? 1 : 0;
    __syncthreads();

    // Initial farthest = index of k-th True, k = rand_start[b] % count.
    if (tid < 32) {
        const int chunk = (n + 31) / 32;
        const int base  = lane * chunk;
        int cnt = 0;
        for (int i = 0; i < chunk; i++) {
            int jj = base + i;
            if (jj < n) cnt += s_mask[jj];
        }
        int inc = cnt;
        #pragma unroll
        for (int off = 1; off < 32; off <<= 1) {
            int v = __shfl_up_sync(FULL_MASK, inc, off);
            if (lane >= off) inc += v;
        }
        const int total = __shfl_sync(FULL_MASK, inc, 31);
        const int k     = rand_start[b] % total;
        const int excl  = inc - cnt;
        if (k >= excl && k < inc) {
            int need = k - excl;
            for (int i = 0; i < chunk; i++) {
                int jj = base + i;
                if (jj < n && s_mask[jj]) {
                    if (need == 0) { s_far = jj; break; }
                    need--;
                }
            }
        }
    }
    __syncthreads();
    int far = s_far;

    const unsigned E_INIT = enc_f32(1e8f);
    uint4 dist = make_uint4(E_INIT, E_INIT, E_INIT, E_INIT);

    const int    nq  = n >> 2;
    const uint4* dmb = (const uint4*)g_dm + (size_t)b * n * nq;

    for (int t = 0; t < m; t++) {
        // Row read first: 8 KB from L2 (dm resident after precompute).
        uint4 v = __ldg(dmb + (size_t)far * nq + tid);
        if (tid == 0) g_qidx[b * m + t] = far;

        dist.x = min(dist.x, v.x);
        dist.y = min(dist.y, v.y);
        dist.z = min(dist.z, v.z);
        dist.w = min(dist.w, v.w);

        // Local argmax over 4 (tie -> lowest j).
        unsigned bk = dist.x; int bj = 0;
        if (dist.y > bk) { bk = dist.y; bj = 1; }
        if (dist.z > bk) { bk = dist.z; bj = 2; }
        if (dist.w > bk) { bk = dist.w; bj = 3; }
        bj += tid << 2;

        // Warp argmax via REDUX; winner lane (lowest lane on tie == lowest j
        // under blocked layout) stores packed candidate directly — no shfl.
        const int buf = (t & 1) << 4;
        unsigned mk   = __reduce_max_sync(FULL_MASK, bk);
        unsigned ball = __ballot_sync(FULL_MASK, bk == mk);
        int src       = __ffs(ball) - 1;
        if (lane == src)
            s_slot[0][buf + warp] = ((unsigned long long)mk << 32) | (unsigned)bj;
        __syncthreads();

        // Redundant final reduce in EVERY warp (lanes 0..15 hold the slots).
        unsigned long long pk = (lane < 16) ? s_slot[0][buf + lane] : 0ull;
        unsigned k2 = (unsigned)(pk >> 32);
        int      j2 = (int)(unsigned)pk;
        unsigned mk2   = __reduce_max_sync(FULL_MASK, k2);
        unsigned ball2 = __ballot_sync(FULL_MASK, k2 == mk2);
        int src2       = __ffs(ball2) - 1;          // lowest warp -> lowest j
        far            = __shfl_sync(FULL_MASK, j2, src2);
    }
}

// ---------------------------------------------------------------------------
// Merged gathers: pairs (sub_abq float4 + sub_edges float2) then small
// (sub_vals float4 chunks + sub_mask) in one launch.
// ---------------------------------------------------------------------------
__global__ void gather_kernel(const float4* __restrict__ abq,
                              const float2* __restrict__ edges,
                              const float4* __restrict__ vals4,
                              const void* __restrict__ mask,
                              float4* __restrict__ out_abq,
                              float2* __restrict__ out_edges,
                              float4* __restrict__ out_vals,
                              float* __restrict__ out_mask,
                              int n, int m, int bs, int c4) {
    int idx = blockIdx.x * blockDim.x + threadIdx.x;
    int total_pairs = bs * m * m;
    if (idx < total_pairs) {
        int j = idx % m;
        int r = idx / m;
        int i = r % m;
        int b = r / m;
        int qi = g_qidx[b * m + i];
        int qj = g_qidx[b * m + j];
        size_t src = ((size_t)b * n + (size_t)qi) * (size_t)n + (size_t)qj;
        out_abq[idx]   = __ldcs(abq + src);
        out_edges[idx] = __ldcs(edges + src);
    } else {
        int k = idx - total_pairs;
        if (k >= bs * m * c4) return;
        int ch = k % c4;
        int r  = k / c4;
        int i  = r % m;
        int b  = r / m;
        int qi = g_qidx[b * m + i];
        out_vals[k] = __ldcs(vals4 + ((size_t)b * n + (size_t)qi) * (size_t)c4 + ch);
        if (ch == 0) {
            int mode = mask_mode(mask);
            out_mask[b * m + i] = mask_at(mask, mode, (long)b * n + qi) ? 1.0f : 0.0f;
        }
    }
}

// ---------------------------------------------------------------------------
// Launch. Inputs: abq_pairs f32 (bs,n,n,4), vals f32 (bs,n,64), mask bool
// (bs,n), edges f32 (bs,n,n,2), rand_start i32 (bs).
// Output: [sub_abq | sub_vals | sub_mask | sub_edges] as f32.
// ---------------------------------------------------------------------------
extern "C" void kernel_launch(void* const* d_in, const int* in_sizes, int n_in,
                              void* d_out, int out_size) {
    const float4* abq   = (const float4*)d_in[0];
    const float4* vals4 = (const float4*)d_in[1];
    const void*   mask  = (const void*)d_in[2];
    const float2* edges = (const float2*)d_in[3];
    const int*    rnd   = (const int*)d_in[4];

    const int bs = in_sizes[4];                 // 4
    const int n  = in_sizes[2] / bs;            // 2048
    const int m  = n / 4;                       // 512
    const int c  = in_sizes[1] / (bs * n);      // 64
    const int c4 = c / 4;

    float* out = (float*)d_out;
    float4* out_abq    = (float4*)out;
    float*  out_vals_f = out + (size_t)bs * m * m * 4;
    float*  out_mask   = out_vals_f + (size_t)bs * m * c;
    float2* out_edges  = (float2*)(out_mask + (size_t)bs * m);

    // 1) Precompute encoded masked-distance matrix (bandwidth-bound ~50us).
    int total4 = bs * n * (n / 4);
    precompute_kernel<<<(total4 + 255) / 256, 256>>>(abq, mask, n, total4);

    // 2) Sequential FPS on the L2-resident encoded matrix.
    fps_kernel<<<bs, 512>>>(mask, rnd, n, m);

    // 3) Merged output gathers.
    int total = bs * m * m + bs * m * c4;
    gather_kernel<<<(total + 255) / 256, 256>>>(
        abq, edges, vals4, mask,
        out_abq, out_edges, (float4*)out_vals_f, out_mask, n, m, bs, c4);
}

// round 6
// speedup vs baseline: 2.5369x; 1.3391x over previous
#include <cuda_runtime.h>
#include <cuda_bf16.h>
#include <math.h>

#define FULL_MASK 0xFFFFFFFFu

// Scratch: chosen FPS indices and the encoded distance matrix
// (bs*n*n = 4*2048*2048 uint32 = 64 MB; fits in GB300's ~126 MB L2).
__device__ int      g_qidx[8192];
__device__ unsigned g_dm[4L * 2048 * 2048];

// ---------------------------------------------------------------------------
// Mask dtype handling (bool may arrive as u8 / i32 / f32; mask[0] is True).
// ---------------------------------------------------------------------------
__device__ __forceinline__ int mask_mode(const void* mask) {
    unsigned u0 = *(const unsigned*)mask;
    if (u0 == 0x3F800000u) return 2;   // f32
    if (u0 == 1u)          return 1;   // i32
    return 0;                          // byte
}
__device__ __forceinline__ bool mask_at(const void* mask, int mode, long idx) {
    if (mode == 0) return ((const unsigned char*)mask)[idx] != 0;
    if (mode == 1) return ((const int*)mask)[idx] != 0;
    return ((const float*)mask)[idx] != 0.0f;
}

// Monotone (order-preserving) float -> uint32 encoding.
__device__ __forceinline__ unsigned enc_f32(float f) {
    unsigned u = __float_as_uint(f);
    unsigned s = (unsigned)((int)u >> 31);        // all-ones if negative
    return u ^ (s | 0x80000000u);
}

// ---------------------------------------------------------------------------
// Precompute: g_dm[b,i,j] = enc( mask[b,j] ? ||abq[b,i,j,:]|| : -100 ).
// One thread per 4 consecutive j (64B load / 16B store, fully coalesced).
// (Exact R2 version: __ldg, default caching.)
// ---------------------------------------------------------------------------
__global__ void precompute_kernel(const float4* __restrict__ abq,
                                  const void* __restrict__ mask,
                                  int n, int total4) {
    int idx = blockIdx.x * blockDim.x + threadIdx.x;
    if (idx >= total4) return;
    const int nq = n >> 2;
    int j4 = idx % nq;
    int r  = idx / nq;
    int b  = r / n;

    const int mode = mask_mode(mask);
    const float4* src = abq + (size_t)idx * 4;
    unsigned out[4];
    #pragma unroll
    for (int k = 0; k < 4; k++) {
        float4 v = __ldg(src + k);
        float nrm = sqrtf(v.x*v.x + v.y*v.y + v.z*v.z + v.w*v.w);
        bool mk = mask_at(mask, mode, (long)b * n + j4 * 4 + k);
        out[k] = enc_f32(mk ? nrm : -100.0f);
    }
    ((uint4*)g_dm)[idx] = make_uint4(out[0], out[1], out[2], out[3]);
}

// ---------------------------------------------------------------------------
// FPS: one block per batch, 512 threads, 4 j's per thread (blocked layout so
// lane order == j order for first-occurrence tie-breaks).
// Per iter: 1 uint4 L2 load, 4 umin, local argmax, REDUX warp argmax,
// ONE barrier, redundant per-warp final reduce (double-buffered smem slots).
// (Exact R2 version.)
// ---------------------------------------------------------------------------
__global__ void __launch_bounds__(512, 1)
fps_kernel(const void* __restrict__ mask, const int* __restrict__ rand_start,
           int n, int m) {
    const int b    = blockIdx.x;
    const int tid  = threadIdx.x;
    const int nthr = blockDim.x;            // 512
    const int lane = tid & 31;
    const int warp = tid >> 5;               // 0..15

    extern __shared__ unsigned char smem[];
    unsigned char* s_mask = smem;                         // n bytes
    unsigned* s_key = (unsigned*)(smem + ((n + 7) & ~7)); // [2][16]
    int*      s_idx = (int*)(s_key + 32);                 // [2][16]
    int*      s_far = s_idx + 32;

    // Stage mask (needed only for the initial k-th-valid index).
    const int  mode  = mask_mode(mask);
    const long mbase = (long)b * n;
    for (int j = tid; j < n; j += nthr)
        s_mask[j] = mask_at(mask, mode, mbase + j) ? 1 : 0;
    __syncthreads();

    // Initial farthest = index of k-th True, k = rand_start[b] % count.
    if (tid < 32) {
        const int chunk = (n + 31) / 32;
        const int base  = lane * chunk;
        int cnt = 0;
        for (int i = 0; i < chunk; i++) {
            int jj = base + i;
            if (jj < n) cnt += s_mask[jj];
        }
        int inc = cnt;
        #pragma unroll
        for (int off = 1; off < 32; off <<= 1) {
            int v = __shfl_up_sync(FULL_MASK, inc, off);
            if (lane >= off) inc += v;
        }
        const int total = __shfl_sync(FULL_MASK, inc, 31);
        const int k     = rand_start[b] % total;
        const int excl  = inc - cnt;
        if (k >= excl && k < inc) {
            int need = k - excl;
            for (int i = 0; i < chunk; i++) {
                int jj = base + i;
                if (jj < n && s_mask[jj]) {
                    if (need == 0) { *s_far = jj; break; }
                    need--;
                }
            }
        }
    }
    __syncthreads();
    int far = *s_far;

    // Encoded running distances (init enc(1e8)).
    const unsigned E_INIT = enc_f32(1e8f);
    uint4 dist = make_uint4(E_INIT, E_INIT, E_INIT, E_INIT);

    const uint4* dmb = (const uint4*)(g_dm) + (size_t)b * n * (n >> 2);

    for (int t = 0; t < m; t++) {
        if (tid == 0) g_qidx[b * m + t] = far;

        // Row read: 8 KB from L2 (whole dm fits in L2 after precompute).
        uint4 v = __ldg(dmb + (size_t)far * (n >> 2) + tid);
        dist.x = min(dist.x, v.x);
        dist.y = min(dist.y, v.y);
        dist.z = min(dist.z, v.z);
        dist.w = min(dist.w, v.w);

        // Local argmax over 4 (tie -> lowest j).
        unsigned bk = dist.x; int bj = 0;
        if (dist.y > bk) { bk = dist.y; bj = 1; }
        if (dist.z > bk) { bk = dist.z; bj = 2; }
        if (dist.w > bk) { bk = dist.w; bj = 3; }
        bj += tid << 2;

        // Warp argmax via REDUX; tie -> lowest lane == lowest j (blocked).
        unsigned mk   = __reduce_max_sync(FULL_MASK, bk);
        unsigned ball = __ballot_sync(FULL_MASK, bk == mk);
        int src       = __ffs(ball) - 1;
        int wj        = __shfl_sync(FULL_MASK, bj, src);
        const int buf = t & 1;
        if (lane == 0) { s_key[buf * 16 + warp] = mk; s_idx[buf * 16 + warp] = wj; }
        __syncthreads();

        // Redundant final reduce in EVERY warp (no second barrier needed:
        // next iter writes the other buffer, and its own barrier fences it).
        unsigned k2 = 0; int j2 = 0;
        if (lane < 16) { k2 = s_key[buf * 16 + lane]; j2 = s_idx[buf * 16 + lane]; }
        unsigned mk2   = __reduce_max_sync(FULL_MASK, k2);
        unsigned ball2 = __ballot_sync(FULL_MASK, k2 == mk2);
        int src2       = __ffs(ball2) - 1;
        far            = __shfl_sync(FULL_MASK, j2, src2);
    }
}

// ---------------------------------------------------------------------------
// Merged gathers: pairs (sub_abq float4 + sub_edges float2) then small
// (sub_vals float4 chunks + sub_mask) in one launch. Runs strictly after fps;
// not on the serial critical path.
// ---------------------------------------------------------------------------
__global__ void gather_kernel(const float4* __restrict__ abq,
                              const float2* __restrict__ edges,
                              const float4* __restrict__ vals4,
                              const void* __restrict__ mask,
                              float4* __restrict__ out_abq,
                              float2* __restrict__ out_edges,
                              float4* __restrict__ out_vals,
                              float* __restrict__ out_mask,
                              int n, int m, int bs, int c4) {
    int idx = blockIdx.x * blockDim.x + threadIdx.x;
    int total_pairs = bs * m * m;
    if (idx < total_pairs) {
        int j = idx % m;
        int r = idx / m;
        int i = r % m;
        int b = r / m;
        int qi = g_qidx[b * m + i];
        int qj = g_qidx[b * m + j];
        size_t src = ((size_t)b * n + (size_t)qi) * (size_t)n + (size_t)qj;
        out_abq[idx]   = __ldg(abq + src);
        out_edges[idx] = __ldg(edges + src);
    } else {
        int k = idx - total_pairs;
        if (k >= bs * m * c4) return;
        int ch = k % c4;
        int r  = k / c4;
        int i  = r % m;
        int b  = r / m;
        int qi = g_qidx[b * m + i];
        out_vals[k] = __ldg(vals4 + ((size_t)b * n + (size_t)qi) * (size_t)c4 + ch);
        if (ch == 0) {
            int mode = mask_mode(mask);
            out_mask[b * m + i] = mask_at(mask, mode, (long)b * n + qi) ? 1.0f : 0.0f;
        }
    }
}

// ---------------------------------------------------------------------------
// Launch. Inputs: abq_pairs f32 (bs,n,n,4), vals f32 (bs,n,64), mask bool
// (bs,n), edges f32 (bs,n,n,2), rand_start i32 (bs).
// Output: [sub_abq | sub_vals | sub_mask | sub_edges] as f32.
// ---------------------------------------------------------------------------
extern "C" void kernel_launch(void* const* d_in, const int* in_sizes, int n_in,
                              void* d_out, int out_size) {
    const float4* abq   = (const float4*)d_in[0];
    const float4* vals4 = (const float4*)d_in[1];
    const void*   mask  = (const void*)d_in[2];
    const float2* edges = (const float2*)d_in[3];
    const int*    rnd   = (const int*)d_in[4];

    const int bs = in_sizes[4];                 // 4
    const int n  = in_sizes[2] / bs;            // 2048
    const int m  = n / 4;                       // 512
    const int c  = in_sizes[1] / (bs * n);      // 64
    const int c4 = c / 4;

    float* out = (float*)d_out;
    float4* out_abq    = (float4*)out;
    float*  out_vals_f = out + (size_t)bs * m * m * 4;
    float*  out_mask   = out_vals_f + (size_t)bs * m * c;
    float2* out_edges  = (float2*)(out_mask + (size_t)bs * m);

    // 1) Precompute encoded masked-distance matrix (bandwidth-bound, ~51us).
    int total4 = bs * n * (n / 4);
    precompute_kernel<<<(total4 + 255) / 256, 256>>>(abq, mask, n, total4);

    // 2) Sequential FPS on the L2-resident encoded matrix (exact R2 loop).
    size_t smem = (size_t)((n + 7) & ~7) + 32 * sizeof(unsigned)
                + 32 * sizeof(int) + sizeof(int);
    fps_kernel<<<bs, 512, smem>>>(mask, rnd, n, m);

    // 3) Merged output gathers.
    int total = bs * m * m + bs * m * c4;
    gather_kernel<<<(total + 255) / 256, 256>>>(
        abq, edges, vals4, mask,
        out_abq, out_edges, (float4*)out_vals_f, out_mask, n, m, bs, c4);
}